// round 17
// baseline (speedup 1.0000x reference)
#include <cuda_runtime.h>

// CWT gaus1, scales {1,3,6}, x:(32,4096,64) f32 -> out:(32,3,4096,64) f32.
//
// Folded form: out_a[b,s,c] = sum_m h_a[m] * x[b, s + start_a + m, c]
//   h_a[m] = -sqrt(a)*(f_a[m-1]-f_a[m]),  f_a[i] = int_psi[floor(i/(a*step))]
// Unified window p rel. to x[s-31]: scale6 m=p, scale3 m=p-15, scale1 m=p-25.
// Truncated taps (validated rel_err 6.55e-5 vs 1e-3 tol): scale6 m in [8,53],
// scale3 m in [4,26], scale1 m in [2,8].
//
// R17 = R16 (split passes, fma.rn.f32x2 compile-time packed constants,
// cp.async fill, hoisted store bases) with TILE_S=72 / T=9: grid becomes
// 57x32 = 1824 blocks = 3.08 waves of the 592 resident (4/SM), vs 2048 =
// 3.46 waves — the 46%-full tail wave (~1.5-2us idle) shrinks to 48 blocks.
// Ragged last tile (rows 4096..4103) handled by zero-guarded loads (already
// present) + predicated stores. Tap set/order unchanged -> rel_err must
// stay exactly 6.550446e-5.

#define S_LEN 4096
#define C_LEN 64
#define TILE_S 72
#define NROWS 133   // TILE_S + 61
#define NT 256
#define T 9         // seq rows per thread (8 groups x 9 = 72)
#define GX 57       // ceil(4096/72)

typedef unsigned long long ull;

// ---------------- compile-time coefficient math ----------------
__host__ __device__ constexpr double cpow2i(int n) {
    double r = 1.0;
    if (n >= 0) { for (int i = 0; i <  n; i++) r *= 2.0; }
    else        { for (int i = 0; i < -n; i++) r *= 0.5; }
    return r;
}
__host__ __device__ constexpr double cexp(double x) {
    const double ln2 = 0.6931471805599453;
    int n = (int)(x / ln2 + (x >= 0.0 ? 0.5 : -0.5));
    double r = x - (double)n * ln2;
    double term = 1.0, sum = 1.0;
    for (int k = 1; k <= 20; k++) { term *= r / (double)k; sum += term; }
    return sum * cpow2i(n);
}
__host__ __device__ constexpr double csqrt_(double x) {
    double g = x > 1.0 ? x : 1.0;
    for (int i = 0; i < 64; i++) g = 0.5 * (g + x / g);
    return g;
}
// Euler-Maclaurin model of numpy cumsum(psi)*step for gaus1 (validated at
// rel_err 4e-7 untruncated / 6.55e-5 truncated, R1-R16).
__host__ __device__ constexpr double ipsi_em(long j) {
    const double step = 10.0 / 1023.0;
    double u = (j >= 1023) ? 5.0 : ((double)j * step - 5.0);
    double e = cexp(-u * u);
    double v = e * (1.0 - step * u + (step * step / 12.0) * (4.0 * u * u - 2.0));
    return v / csqrt_(csqrt_(3.141592653589793 / 2.0));   // (pi/2)^(1/4)
}
__host__ __device__ constexpr float f_at(int a, int i, int L) {
    if (i < 0 || i >= L) return 0.0f;
    const double step = 10.0 / 1023.0;
    double as_ = (double)a * step;          // matches numpy a*step (f64)
    long j = (long)((double)i / as_);       // matches arange/(a*step) astype(int64)
    return (float)ipsi_em(j);
}
__host__ __device__ constexpr float hval(int a, int L, int m) {
    float fm1 = f_at(a, m - 1, L), fm = f_at(a, m, L);
    return -(float)csqrt_((double)a) * (fm1 - fm);   // f32 math like reference
}
// exact constexpr float->bits (taps are normal floats, mantissa integer-exact)
__host__ __device__ constexpr unsigned int f2b(float v) {
    if (v == 0.0f) return 0u;
    unsigned int s = 0; double a = (double)v;
    if (a < 0.0) { s = 0x80000000u; a = -a; }
    int e = 0;
    while (a >= 2.0) { a *= 0.5; e++; }
    while (a < 1.0)  { a *= 2.0; e--; }
    unsigned long long m = (unsigned long long)(a * 8388608.0);  // exact
    return s | ((unsigned int)(e + 127) << 23) | ((unsigned int)m & 0x7FFFFFu);
}
__host__ __device__ constexpr ull pk(float v) {
    unsigned int b = f2b(v);
    return ((ull)b << 32) | (ull)b;
}

__device__ __forceinline__ void ffma2(ull &d, ull a, ull b) {
    asm("fma.rn.f32x2 %0, %1, %2, %0;" : "+l"(d) : "l"(a), "l"(b));
}
__device__ __forceinline__ unsigned smem_u32(const void* p) {
    unsigned a;
    asm("{ .reg .u64 t; cvta.to.shared.u64 t, %1; cvt.u32.u64 %0, t; }"
        : "=r"(a) : "l"(p));
    return a;
}
__device__ __forceinline__ void cp_async16(unsigned d, const void* g) {
    asm volatile("cp.async.ca.shared.global [%0], [%1], 16;"
                 :: "r"(d), "l"(g) : "memory");
}

// ---------------- one pass over a (truncated) tap range ----------------
// P = unified window index; filter tap index m = P - F0. Ring of 11 rows:
// at iter P holds rows P..P+10 (mod 11), uses rows P..P+8, prefetches row
// P+10 (consumed at iter P+2).
template<int P, int F0, int PEND, int A, int L>
__device__ __forceinline__ void pass_step(const float (*xs)[C_LEN], int rbase, int pr,
                                          ull (&win)[11], ull (&Acc)[T]) {
    if constexpr (P < PEND) {
        if constexpr (P + 10 <= PEND + 7)   // rows needed go up to PEND-1+8
            win[(P + 10) % 11] = *(const ull*)&xs[rbase + P + 10][pr * 2];
        constexpr ull c = pk(hval(A, L, P - F0));
        #pragma unroll
        for (int t = 0; t < T; t++)
            ffma2(Acc[t], win[(P + t) % 11], c);
        pass_step<P + 1, F0, PEND, A, L>(xs, rbase, pr, win, Acc);
    }
}

template<int PSTART, int F0, int PEND, int A, int L>
__device__ __forceinline__ void do_pass(const float (*xs)[C_LEN], int rbase, int pr,
                                        ull (&Acc)[T]) {
    ull win[11];
    #pragma unroll
    for (int r = 0; r < 10; r++)
        win[(PSTART + r) % 11] = *(const ull*)&xs[rbase + PSTART + r][pr * 2];
    pass_step<PSTART, F0, PEND, A, L>(xs, rbase, pr, win, Acc);
}

// ---------------- kernel ----------------
__global__ void __launch_bounds__(NT)
cwt_kernel(const float* __restrict__ x, float* __restrict__ out) {
    __shared__ float xs[NROWS][C_LEN];

    const int tid = threadIdx.x;
    const int b   = blockIdx.y;
    const int s0  = blockIdx.x * TILE_S;

    // ---- async fill of smem tile (rows s0-31 .. s0+101, zero-padded) ----
    {
        const float4* xg = (const float4*)x + (size_t)b * (S_LEN * (C_LEN / 4));
        const unsigned sb = smem_u32(&xs[0][0]);
        #pragma unroll
        for (int k = 0; k < 9; k++) {
            int f = tid + k * NT;
            if (f < NROWS * 16) {
                int gs = s0 - 31 + (f >> 4);
                unsigned d = sb + f * 16;
                if (gs >= 0 && gs < S_LEN)
                    cp_async16(d, (const void*)(xg + gs * 16 + (f & 15)));
                else
                    asm volatile("st.shared.v4.b32 [%0], {%1,%1,%1,%1};"
                                 :: "r"(d), "r"(0) : "memory");
            }
        }
        asm volatile("cp.async.commit_group;" ::: "memory");
        asm volatile("cp.async.wait_group 0;" ::: "memory");
    }
    __syncthreads();

    // ---- compute: thread = 2 channels x 9 seq rows, one scale per pass ----
    const int pr    = tid & 31;          // channel pair 0..31
    const int sg    = tid >> 5;          // seq group 0..7
    const int rbase = sg * T;

    const int srow = s0 + rbase;
    const size_t plane = (size_t)S_LEN * (C_LEN / 2);
    // hoisted per-scale store bases for this thread's first row
    ull* o1 = (ull*)out + (size_t)b * 3 * plane
                        + (size_t)srow * (C_LEN / 2) + pr;
    ull* o3 = o1 + plane;
    ull* o6 = o3 + plane;

    {   // scale 6: full taps m=0..61; kept m in [8,53] -> P in [8,54)
        ull A6[T] = {0,0,0,0,0,0,0,0,0};
        do_pass<8, 0, 54, 6, 61>(xs, rbase, pr, A6);
        #pragma unroll
        for (int t = 0; t < T; t++)
            if (srow + t < S_LEN)
                o6[(size_t)t * (C_LEN / 2)] = A6[t];
    }
    {   // scale 3: taps at P=m+15; kept m in [4,26] -> P in [19,42)
        ull A3[T] = {0,0,0,0,0,0,0,0,0};
        do_pass<19, 15, 42, 3, 31>(xs, rbase, pr, A3);
        #pragma unroll
        for (int t = 0; t < T; t++)
            if (srow + t < S_LEN)
                o3[(size_t)t * (C_LEN / 2)] = A3[t];
    }
    {   // scale 1: taps at P=m+25; kept m in [2,8] -> P in [27,34)
        ull A1[T] = {0,0,0,0,0,0,0,0,0};
        do_pass<27, 25, 34, 1, 11>(xs, rbase, pr, A1);
        #pragma unroll
        for (int t = 0; t < T; t++)
            if (srow + t < S_LEN)
                o1[(size_t)t * (C_LEN / 2)] = A1[t];
    }
}

extern "C" void kernel_launch(void* const* d_in, const int* in_sizes, int n_in,
                              void* d_out, int out_size) {
    const float* x = (const float*)d_in[0];
    float* out = (float*)d_out;
    dim3 grid(GX, 32);   // (57 seq tiles, 32 batches) = 1824 blocks
    cwt_kernel<<<grid, NT>>>(x, out);
}